// round 7
// baseline (speedup 1.0000x reference)
#include <cuda_runtime.h>

// -------- static scratch (no allocations allowed) --------
// Zero-initialized at module load; reset by k2/k3 each call so every call
// (including graph replays) observes zeroed counters.
#define CAPR 64
#define CAPC 64
#define CAPE 320
#define MAXN 4096

__device__ int   g_cnt_row[MAXN];          // CM CSR bucket counts
__device__ float g_rowsum[MAXN];           // S_k = sum of row k's scaled weights
__device__ int2  g_rbuf[MAXN * CAPR];      // (col, bits(-v))
__device__ int   g_cnt_col[MAXN];          // CM contributor counts
__device__ int2  g_cbuf[MAXN * CAPC];      // (src row k, bits(-v))
__device__ int   g_cnt_ext[MAXN];          // LOC/IU item counts per output row
__device__ int2  g_ebuf[MAXN * CAPE];      // (col, bits(val))

// ============ K1: bin everything ============================================
// Blocks [0,nbCM): CM COO -> row buckets + contributor buckets + rowsums.
// Blocks [nbCM,+nbLoc): LOC (mi,j) -> 4 row-binned (col,val) items.
// Blocks [..,+nbIu):    IU  (mi,j) -> 4 row-binned (col,val) items.
__global__ void k1_bin(const int* __restrict__ row,
                       const int* __restrict__ col,
                       const float* __restrict__ data,
                       const float* __restrict__ cmw, int nnz,
                       const int* __restrict__ locInd,
                       const float* __restrict__ locFl,
                       const float* __restrict__ locw,
                       int mloc, const int* __restrict__ widthp,
                       const int* __restrict__ iuInd,
                       const float* __restrict__ iuFl,
                       const int* __restrict__ iuNb,
                       const float* __restrict__ iuw,
                       int miu, int nbCM, int nbLoc) {
    int b = blockIdx.x;
    if (b < nbCM) {
        int t = b * blockDim.x + threadIdx.x;
        if (t >= nnz) return;
        int r = row[t];
        int c = col[t];
        float v = data[t] * cmw[r];
        int s = atomicAdd(&g_cnt_row[r], 1);
        if (s < CAPR) g_rbuf[r * CAPR + s] = make_int2(c, __float_as_int(-v));
        atomicAdd(&g_rowsum[r], v);
        int s2 = atomicAdd(&g_cnt_col[c], 1);
        if (s2 < CAPC) g_cbuf[c * CAPC + s2] = make_int2(r, __float_as_int(-v));
        return;
    }
    b -= nbCM;
    if (b < nbLoc) {
        int t = b * blockDim.x + threadIdx.x;
        if (t >= mloc * 9) return;
        int mi = t / 9, j = t - mi * 9;
        int W = widthp[0];
        int ind = locInd[mi];
        float h = 0.5f * locFl[(size_t)j * 9 * mloc + mi] * locw[ind];
        int r = ind - 1 - W;
        int c = ind + (j / 3 - 1) + (j % 3 - 1) * W;
        int s = atomicAdd(&g_cnt_ext[r], 2);
        if (s + 1 < CAPE) {
            g_ebuf[r * CAPE + s]     = make_int2(c, __float_as_int(-h));
            g_ebuf[r * CAPE + s + 1] = make_int2(r, __float_as_int(h));
        }
        int s2 = atomicAdd(&g_cnt_ext[c], 2);
        if (s2 + 1 < CAPE) {
            g_ebuf[c * CAPE + s2]     = make_int2(r, __float_as_int(-h));
            g_ebuf[c * CAPE + s2 + 1] = make_int2(c, __float_as_int(h));
        }
        return;
    }
    b -= nbLoc;
    {
        int t = b * blockDim.x + threadIdx.x;
        if (t >= miu * 5) return;
        int mi = t / 5, j = t - mi * 5;
        int r = iuInd[mi];
        float h = 0.5f * iuFl[mi * 5 + j] * iuw[r];
        int c = iuNb[mi * 5 + j];
        int s = atomicAdd(&g_cnt_ext[r], 2);
        if (s + 1 < CAPE) {
            g_ebuf[r * CAPE + s]     = make_int2(c, __float_as_int(-h));
            g_ebuf[r * CAPE + s + 1] = make_int2(r, __float_as_int(h));
        }
        int s2 = atomicAdd(&g_cnt_ext[c], 2);
        if (s2 + 1 < CAPE) {
            g_ebuf[c * CAPE + s2]     = make_int2(r, __float_as_int(-h));
            g_ebuf[c * CAPE + s2 + 1] = make_int2(c, __float_as_int(h));
        }
    }
}

// ============ K2: build the COMPLETE output row a of A in smem, store once ==
__global__ void __launch_bounds__(512) k2_rows(
        float* __restrict__ A, float* __restrict__ bvec, int n,
        const float* __restrict__ ku, const float* __restrict__ conf,
        const float* __restrict__ lmb, const float* __restrict__ known,
        const float* __restrict__ kToU) {
    __shared__ float rowbuf[MAXN];
    __shared__ int   skk[CAPC + 1];
    __shared__ float scf[CAPC + 1];
    int a = blockIdx.x;
    int tid = threadIdx.x;

    // read counts into registers before any reset can happen
    int cc = g_cnt_col[a]; if (cc > CAPC) cc = CAPC;
    int ce = g_cnt_ext[a]; if (ce > CAPE) ce = CAPE;

    float4* rb4 = (float4*)rowbuf;
    float4 z = make_float4(0.f, 0.f, 0.f, 0.f);
    for (int i = tid; i < (n >> 2); i += blockDim.x) rb4[i] = z;

    for (int i = tid; i < cc; i += blockDim.x) {
        int2 e = g_cbuf[a * CAPC + i];
        skk[i] = e.x;
        scf[i] = __int_as_float(e.y);
    }
    if (tid == 0) {
        skk[cc] = a;            // virtual diagonal contributor (a, +S_a)
        scf[cc] = g_rowsum[a];
    }
    __syncthreads();            // all threads past their count reads
    if (tid == 0) { g_cnt_col[a] = 0; g_cnt_ext[a] = 0; }  // reset for next call

    // ---- CM: A[a,:] += sum_k Lcm[k,a] * Lcm[k,:]
    int warp = tid >> 5, lane = tid & 31, nw = blockDim.x >> 5;
    for (int it = warp; it <= cc; it += nw) {
        int   k    = skk[it];
        float coef = scf[it];
        int ck = g_cnt_row[k]; if (ck > CAPR) ck = CAPR;
        for (int j = lane; j < ck; j += 32) {
            int2 e = g_rbuf[k * CAPR + j];
            atomicAdd(&rowbuf[e.x], coef * __int_as_float(e.y));
        }
        if (lane == 0)          // virtual diagonal entry of source row k
            atomicAdd(&rowbuf[k], coef * g_rowsum[k]);
    }

    // ---- LOC/IU binned items
    for (int i = tid; i < ce; i += blockDim.x) {
        int2 e = g_ebuf[a * CAPE + i];
        atomicAdd(&rowbuf[e.x], __int_as_float(e.y));
    }

    // ---- diagonal regularization + b
    if (tid == 0) {
        float d = ku[a] * conf[a] + lmb[0] * known[a];
        atomicAdd(&rowbuf[a], d);
        bvec[a] = d * kToU[a];
    }
    __syncthreads();

    float4* dst = (float4*)(A + (size_t)a * n);
    for (int i = tid; i < (n >> 2); i += blockDim.x) dst[i] = rb4[i];
}

// ============ K3: reset shared-reader scratch + tail-poison cleanup =========
__global__ void k3_reset(float* __restrict__ out, int n, long total) {
    int i = blockIdx.x * blockDim.x + threadIdx.x;
    if (i < n) { g_cnt_row[i] = 0; g_rowsum[i] = 0.f; }
    long base = (long)n * n + n;
    long extra = total - base;
    if (extra > 0) {
        long p = (long)blockIdx.x * blockDim.x + threadIdx.x;
        if (p < extra) out[base + p] = 0.f;
    }
}

extern "C" void kernel_launch(void* const* d_in, const int* in_sizes, int n_in,
                              void* d_out, int out_size) {
    // 0 height, 1 width, 2 CM_weights, 3 LOC_weights, 4 IU_weights,
    // 5 KU_weights, 6 lmbda, 7 kToUconf, 8 known, 9 kToU,
    // 10 Wcm_row, 11 Wcm_col, 12 Wcm_data, 13 LOC_inInd, 14 LOC_flows,
    // 15 IU_inInd, 16 IU_flows, 17 IU_neighInd
    const int*   width   = (const int*)d_in[1];
    const float* CMw     = (const float*)d_in[2];
    const float* LOCw    = (const float*)d_in[3];
    const float* IUw     = (const float*)d_in[4];
    const float* KUw     = (const float*)d_in[5];
    const float* lmbda   = (const float*)d_in[6];
    const float* conf    = (const float*)d_in[7];
    const float* known   = (const float*)d_in[8];
    const float* kToU    = (const float*)d_in[9];
    const int*   wr      = (const int*)d_in[10];
    const int*   wc      = (const int*)d_in[11];
    const float* wd      = (const float*)d_in[12];
    const int*   locInd  = (const int*)d_in[13];
    const float* locFl   = (const float*)d_in[14];
    const int*   iuInd   = (const int*)d_in[15];
    const float* iuFl    = (const float*)d_in[16];
    const int*   iuNb    = (const int*)d_in[17];

    int N    = in_sizes[2];
    int NNZ  = in_sizes[10];
    int MLOC = in_sizes[13];
    int MIU  = in_sizes[15];

    float* A = (float*)d_out;
    float* b = A + (size_t)N * N;
    long total = (long)out_size;

    const int T = 256;
    int nbCM  = (NNZ + T - 1) / T;
    int nbLoc = (MLOC * 9 + T - 1) / T;
    int nbIu  = (MIU * 5 + T - 1) / T;
    k1_bin<<<nbCM + nbLoc + nbIu, T>>>(wr, wc, wd, CMw, NNZ,
                                       locInd, locFl, LOCw, MLOC, width,
                                       iuInd, iuFl, iuNb, IUw, MIU,
                                       nbCM, nbLoc);

    k2_rows<<<N, 512>>>(A, b, N, KUw, conf, lmbda, known, kToU);

    k3_reset<<<(N + T - 1) / T, T>>>(A, N, total);
}

// round 8
// speedup vs baseline: 1.0537x; 1.0537x over previous
#include <cuda_runtime.h>

#define CAPR 64
#define CAPC 64
#define CAPE 320
#define MAXN 4096
#define NB   1024
#define NT   256

// -------- static scratch (no allocations allowed) --------
// Zero-initialized at module load; counters reset in-kernel / by k3 so every
// call (including graph replays) observes zeroed state.
__device__ int  g_cnt_row[MAXN];          // CM CSR bucket counts
__device__ int2 g_rbuf[MAXN * CAPR];      // (col, bits(-v))
__device__ int  g_cnt_col[MAXN];          // CM contributor counts
__device__ int2 g_cbuf[MAXN * CAPC];      // (src row k, bits(-v))
__device__ int  g_cnt_ext[MAXN];          // LOC/IU items per output row
__device__ int2 g_ebuf[MAXN * CAPE];      // (col, bits(val))
__device__ int  g_bar;                    // grid barrier arrivals
__device__ int  g_done;                   // exit counter (resets g_bar)

__global__ void __launch_bounds__(NT, 8) k_main(
        float* __restrict__ A, float* __restrict__ bvec, int n,
        const int* __restrict__ row, const int* __restrict__ col,
        const float* __restrict__ data, const float* __restrict__ cmw, int nnz,
        const int* __restrict__ locInd, const float* __restrict__ locFl,
        const float* __restrict__ locw, int mloc, const int* __restrict__ widthp,
        const int* __restrict__ iuInd, const float* __restrict__ iuFl,
        const int* __restrict__ iuNb, const float* __restrict__ iuw, int miu,
        const float* __restrict__ ku, const float* __restrict__ conf,
        const float* __restrict__ lmb, const float* __restrict__ known,
        const float* __restrict__ kToU) {
    __shared__ float rowbuf[MAXN];
    __shared__ int   skk[CAPC];
    __shared__ float scf[CAPC];

    int tid = threadIdx.x;

    // ================= Phase 1: bin everything =================
    {
        int t = blockIdx.x * NT + tid;
        if (t < nnz) {
            int r = row[t];
            int c = col[t];
            float v = data[t] * cmw[r];
            int s = atomicAdd(&g_cnt_row[r], 1);
            if (s < CAPR) g_rbuf[r * CAPR + s] = make_int2(c, __float_as_int(-v));
            int s2 = atomicAdd(&g_cnt_col[c], 1);
            if (s2 < CAPC) g_cbuf[c * CAPC + s2] = make_int2(r, __float_as_int(-v));
        } else {
            int t2 = t - nnz;
            if (t2 < mloc * 9) {
                int mi = t2 / 9, j = t2 - mi * 9;
                int W = widthp[0];
                int ind = locInd[mi];
                float h = 0.5f * locFl[(size_t)j * 9 * mloc + mi] * locw[ind];
                int r = ind - 1 - W;
                int c = ind + (j / 3 - 1) + (j % 3 - 1) * W;
                int s = atomicAdd(&g_cnt_ext[r], 2);
                if (s + 1 < CAPE) {
                    g_ebuf[r * CAPE + s]     = make_int2(c, __float_as_int(-h));
                    g_ebuf[r * CAPE + s + 1] = make_int2(r, __float_as_int(h));
                }
                int s2 = atomicAdd(&g_cnt_ext[c], 2);
                if (s2 + 1 < CAPE) {
                    g_ebuf[c * CAPE + s2]     = make_int2(r, __float_as_int(-h));
                    g_ebuf[c * CAPE + s2 + 1] = make_int2(c, __float_as_int(h));
                }
            } else {
                int t3 = t2 - mloc * 9;
                if (t3 < miu * 5) {
                    int mi = t3 / 5, j = t3 - mi * 5;
                    int r = iuInd[mi];
                    float h = 0.5f * iuFl[mi * 5 + j] * iuw[r];
                    int c = iuNb[mi * 5 + j];
                    int s = atomicAdd(&g_cnt_ext[r], 2);
                    if (s + 1 < CAPE) {
                        g_ebuf[r * CAPE + s]     = make_int2(c, __float_as_int(-h));
                        g_ebuf[r * CAPE + s + 1] = make_int2(r, __float_as_int(h));
                    }
                    int s2 = atomicAdd(&g_cnt_ext[c], 2);
                    if (s2 + 1 < CAPE) {
                        g_ebuf[c * CAPE + s2]     = make_int2(r, __float_as_int(-h));
                        g_ebuf[c * CAPE + s2 + 1] = make_int2(c, __float_as_int(h));
                    }
                }
            }
        }
    }

    // ================= Grid barrier (all 1024 blocks resident) =================
    __threadfence();
    __syncthreads();
    if (tid == 0) {
        atomicAdd(&g_bar, 1);
        volatile int* p = &g_bar;
        while (*p < NB) { }
    }
    __syncthreads();
    __threadfence();

    // ================= Phase 2: build complete rows, store once ================
    int warp = tid >> 5, lane = tid & 31;
    float4* rb4 = (float4*)rowbuf;
    int n4 = n >> 2;

    for (int a = blockIdx.x; a < n; a += NB) {
        int cc = g_cnt_col[a]; if (cc > CAPC) cc = CAPC;
        int ce = g_cnt_ext[a]; if (ce > CAPE) ce = CAPE;

        float4 z = make_float4(0.f, 0.f, 0.f, 0.f);
        for (int i = tid; i < n4; i += NT) rb4[i] = z;
        if (tid < cc) {
            int2 e = g_cbuf[a * CAPC + tid];
            skk[tid] = e.x;
            scf[tid] = __int_as_float(e.y);
        }
        __syncthreads();

        // CM contributors (one warp per contributor; it==cc is the virtual
        // diagonal contributor with coefficient S_a computed on the fly).
        for (int it = warp; it <= cc; it += NT / 32) {
            bool virt = (it == cc);
            int k = virt ? a : skk[it];
            int ck = g_cnt_row[k]; if (ck > CAPR) ck = CAPR;
            int2 e1 = (lane < ck) ? g_rbuf[k * CAPR + lane] : make_int2(0, 0);
            bool has2 = (lane + 32 < ck);
            int2 e2 = has2 ? g_rbuf[k * CAPR + lane + 32] : make_int2(0, 0);
            float v1 = __int_as_float(e1.y);
            float v2 = __int_as_float(e2.y);
            float s = v1 + v2;                 // sum of (-v) entries
            #pragma unroll
            for (int o = 16; o; o >>= 1) s += __shfl_xor_sync(0xffffffffu, s, o);
            float S = -s;                      // rowsum of source row k
            float coef = virt ? S : scf[it];
            if (lane < ck) atomicAdd(&rowbuf[e1.x], coef * v1);
            if (has2)      atomicAdd(&rowbuf[e2.x], coef * v2);
            if (lane == 0) atomicAdd(&rowbuf[k], coef * S);
        }

        // LOC / IU binned items
        for (int i = tid; i < ce; i += NT) {
            int2 e = g_ebuf[a * CAPE + i];
            atomicAdd(&rowbuf[e.x], __int_as_float(e.y));
        }

        // diagonal regularization + b, and reset this row's private counters
        if (tid == 0) {
            float d = ku[a] * conf[a] + lmb[0] * known[a];
            atomicAdd(&rowbuf[a], d);
            bvec[a] = d * kToU[a];
            g_cnt_col[a] = 0;
            g_cnt_ext[a] = 0;
        }
        __syncthreads();

        float4* dst = (float4*)(A + (size_t)a * n);
        for (int i = tid; i < n4; i += NT) __stcs(dst + i, rb4[i]);
        __syncthreads();
    }

    // ================= Exit: last block resets barrier state ==================
    if (tid == 0) {
        __threadfence();
        int d = atomicAdd(&g_done, 1);
        if (d == NB - 1) {
            g_bar = 0;
            g_done = 0;
            __threadfence();
        }
    }
}

// Reset the counters that phase 2 reads cross-block, plus tail-poison cleanup.
__global__ void k3_reset(float* __restrict__ out, int n, long total) {
    int i = blockIdx.x * blockDim.x + threadIdx.x;
    if (i < n) g_cnt_row[i] = 0;
    long base = (long)n * n + n;
    long extra = total - base;
    if (extra > 0) {
        long p = (long)blockIdx.x * blockDim.x + threadIdx.x;
        if (p < extra) out[base + p] = 0.f;
    }
}

extern "C" void kernel_launch(void* const* d_in, const int* in_sizes, int n_in,
                              void* d_out, int out_size) {
    // 0 height, 1 width, 2 CM_weights, 3 LOC_weights, 4 IU_weights,
    // 5 KU_weights, 6 lmbda, 7 kToUconf, 8 known, 9 kToU,
    // 10 Wcm_row, 11 Wcm_col, 12 Wcm_data, 13 LOC_inInd, 14 LOC_flows,
    // 15 IU_inInd, 16 IU_flows, 17 IU_neighInd
    const int*   width   = (const int*)d_in[1];
    const float* CMw     = (const float*)d_in[2];
    const float* LOCw    = (const float*)d_in[3];
    const float* IUw     = (const float*)d_in[4];
    const float* KUw     = (const float*)d_in[5];
    const float* lmbda   = (const float*)d_in[6];
    const float* conf    = (const float*)d_in[7];
    const float* known   = (const float*)d_in[8];
    const float* kToU    = (const float*)d_in[9];
    const int*   wr      = (const int*)d_in[10];
    const int*   wc      = (const int*)d_in[11];
    const float* wd      = (const float*)d_in[12];
    const int*   locInd  = (const int*)d_in[13];
    const float* locFl   = (const float*)d_in[14];
    const int*   iuInd   = (const int*)d_in[15];
    const float* iuFl    = (const float*)d_in[16];
    const int*   iuNb    = (const int*)d_in[17];

    int N    = in_sizes[2];
    int NNZ  = in_sizes[10];
    int MLOC = in_sizes[13];
    int MIU  = in_sizes[15];

    float* A = (float*)d_out;
    float* b = A + (size_t)N * N;
    long total = (long)out_size;

    k_main<<<NB, NT>>>(A, b, N,
                       wr, wc, wd, CMw, NNZ,
                       locInd, locFl, LOCw, MLOC, width,
                       iuInd, iuFl, iuNb, IUw, MIU,
                       KUw, conf, lmbda, known, kToU);
    k3_reset<<<(N + 255) / 256, 256>>>(A, N, total);
}

// round 9
// speedup vs baseline: 1.3942x; 1.3231x over previous
#include <cuda_runtime.h>

#define CAPR 64
#define CAPC 64
#define CAPE 320
#define MAXN 4096

// -------- static scratch (no allocations allowed) --------
// Zero-initialized at module load; counters reset in k2/k3 so every call
// (including graph replays) observes zeroed state.
__device__ int   g_cnt_row[MAXN];          // CM CSR bucket counts
__device__ int2  g_rbuf[MAXN * CAPR];      // (col, bits(-v))
__device__ int   g_cnt_col[MAXN];          // CM contributor counts
__device__ int2  g_cbuf[MAXN * CAPC];      // (src row k, bits(-v))
__device__ int   g_cnt_ext[MAXN];          // LOC/IU off-diag items per row
__device__ int2  g_ebuf[MAXN * CAPE];      // (col, bits(val))
__device__ float g_rowsum[MAXN];           // S_k of CM row k
__device__ float g_diag[MAXN];             // LOC/IU diagonal accumulation

// ============ K1: bin everything ============================================
// Blocks [0,nbCM): CM COO (2 items/thread) -> row + contributor buckets,
//                  rowsum via no-return RED.
// Blocks [nbCM,+nbLoc): LOC -> 2 off-diag bucket items + 2 diag REDs.
// Blocks [..,+nbIu):    IU  -> same.
__global__ void k1_bin(const int* __restrict__ row,
                       const int* __restrict__ col,
                       const float* __restrict__ data,
                       const float* __restrict__ cmw, int nnz, int cmStride,
                       const int* __restrict__ locInd,
                       const float* __restrict__ locFl,
                       const float* __restrict__ locw,
                       int mloc, const int* __restrict__ widthp,
                       const int* __restrict__ iuInd,
                       const float* __restrict__ iuFl,
                       const int* __restrict__ iuNb,
                       const float* __restrict__ iuw,
                       int miu, int nbCM, int nbLoc) {
    int b = blockIdx.x;
    if (b < nbCM) {
        int t0 = b * blockDim.x + threadIdx.x;
        #pragma unroll
        for (int rep = 0; rep < 2; rep++) {
            int t = t0 + rep * cmStride;
            if (t < nnz) {
                int r = row[t];
                int c = col[t];
                float v = data[t] * cmw[r];
                int s = atomicAdd(&g_cnt_row[r], 1);
                if (s < CAPR) g_rbuf[r * CAPR + s] = make_int2(c, __float_as_int(-v));
                int s2 = atomicAdd(&g_cnt_col[c], 1);
                if (s2 < CAPC) g_cbuf[c * CAPC + s2] = make_int2(r, __float_as_int(-v));
                atomicAdd(&g_rowsum[r], v);   // no-return RED
            }
        }
        return;
    }
    b -= nbCM;
    if (b < nbLoc) {
        int t = b * blockDim.x + threadIdx.x;
        if (t >= mloc * 9) return;
        int mi = t / 9, j = t - mi * 9;
        int W = widthp[0];
        int ind = locInd[mi];
        float h = 0.5f * locFl[(size_t)j * 9 * mloc + mi] * locw[ind];
        int r = ind - 1 - W;
        int c = ind + (j / 3 - 1) + (j % 3 - 1) * W;
        int s = atomicAdd(&g_cnt_ext[r], 1);
        if (s < CAPE) g_ebuf[r * CAPE + s] = make_int2(c, __float_as_int(-h));
        int s2 = atomicAdd(&g_cnt_ext[c], 1);
        if (s2 < CAPE) g_ebuf[c * CAPE + s2] = make_int2(r, __float_as_int(-h));
        atomicAdd(&g_diag[r], h);             // no-return REDs
        atomicAdd(&g_diag[c], h);
        return;
    }
    b -= nbLoc;
    {
        int t = b * blockDim.x + threadIdx.x;
        if (t >= miu * 5) return;
        int mi = t / 5, j = t - mi * 5;
        int r = iuInd[mi];
        float h = 0.5f * iuFl[mi * 5 + j] * iuw[r];
        int c = iuNb[mi * 5 + j];
        int s = atomicAdd(&g_cnt_ext[r], 1);
        if (s < CAPE) g_ebuf[r * CAPE + s] = make_int2(c, __float_as_int(-h));
        int s2 = atomicAdd(&g_cnt_ext[c], 1);
        if (s2 < CAPE) g_ebuf[c * CAPE + s2] = make_int2(r, __float_as_int(-h));
        atomicAdd(&g_diag[r], h);
        atomicAdd(&g_diag[c], h);
    }
}

// ============ K2: one 128-thread block builds one complete row of A =========
__global__ void __launch_bounds__(128) k2_rows(
        float* __restrict__ A, float* __restrict__ bvec, int n,
        const float* __restrict__ ku, const float* __restrict__ conf,
        const float* __restrict__ lmb, const float* __restrict__ known,
        const float* __restrict__ kToU) {
    __shared__ float rowbuf[MAXN];
    __shared__ int   skk[CAPC];
    __shared__ float scf[CAPC];

    int a = blockIdx.x;
    int tid = threadIdx.x;
    int warp = tid >> 5, lane = tid & 31;

    int cc = g_cnt_col[a]; if (cc > CAPC) cc = CAPC;
    int ce = g_cnt_ext[a]; if (ce > CAPE) ce = CAPE;

    float4* rb4 = (float4*)rowbuf;
    float4 z = make_float4(0.f, 0.f, 0.f, 0.f);
    int n4 = n >> 2;
    #pragma unroll 4
    for (int i = tid; i < n4; i += 128) rb4[i] = z;

    if (tid < cc) {
        int2 e = g_cbuf[a * CAPC + tid];
        skk[tid] = e.x;
        scf[tid] = __int_as_float(e.y);
    }
    __syncthreads();

    // CM contributors: A[a,:] += coef_k * Lcm[k,:] (it == cc is the virtual
    // diagonal contributor of source row a, coefficient S_a).
    for (int it = warp; it <= cc; it += 4) {
        bool virt = (it == cc);
        int k      = virt ? a : skk[it];
        float Sk   = g_rowsum[k];
        float coef = virt ? Sk : scf[it];
        int ck = g_cnt_row[k]; if (ck > CAPR) ck = CAPR;
        if (lane < ck) {
            int2 e = g_rbuf[k * CAPR + lane];
            atomicAdd(&rowbuf[e.x], coef * __int_as_float(e.y));
        }
        if (lane + 32 < ck) {
            int2 e = g_rbuf[k * CAPR + lane + 32];
            atomicAdd(&rowbuf[e.x], coef * __int_as_float(e.y));
        }
        if (lane == 0) atomicAdd(&rowbuf[k], coef * Sk);
    }

    // LOC/IU off-diagonal items
    for (int i = tid; i < ce; i += 128) {
        int2 e = g_ebuf[a * CAPE + i];
        atomicAdd(&rowbuf[e.x], __int_as_float(e.y));
    }

    // diagonal (LOC/IU accumulated + regularization) + b; reset row-private state
    if (tid == 0) {
        float d = ku[a] * conf[a] + lmb[0] * known[a];
        atomicAdd(&rowbuf[a], d + g_diag[a]);
        bvec[a] = d * kToU[a];
        g_diag[a]    = 0.f;
        g_cnt_col[a] = 0;
        g_cnt_ext[a] = 0;
    }
    __syncthreads();

    float4* dst = (float4*)(A + (size_t)a * n);
    #pragma unroll 4
    for (int i = tid; i < n4; i += 128) __stcs(dst + i, rb4[i]);
}

// ============ K3: reset cross-block-read scratch + tail-poison cleanup ======
__global__ void k3_reset(float* __restrict__ out, int n, long total) {
    int i = blockIdx.x * blockDim.x + threadIdx.x;
    if (i < n) { g_cnt_row[i] = 0; g_rowsum[i] = 0.f; }
    long base = (long)n * n + n;
    long extra = total - base;
    if (extra > 0) {
        long p = (long)blockIdx.x * blockDim.x + threadIdx.x;
        if (p < extra) out[base + p] = 0.f;
    }
}

extern "C" void kernel_launch(void* const* d_in, const int* in_sizes, int n_in,
                              void* d_out, int out_size) {
    // 0 height, 1 width, 2 CM_weights, 3 LOC_weights, 4 IU_weights,
    // 5 KU_weights, 6 lmbda, 7 kToUconf, 8 known, 9 kToU,
    // 10 Wcm_row, 11 Wcm_col, 12 Wcm_data, 13 LOC_inInd, 14 LOC_flows,
    // 15 IU_inInd, 16 IU_flows, 17 IU_neighInd
    const int*   width   = (const int*)d_in[1];
    const float* CMw     = (const float*)d_in[2];
    const float* LOCw    = (const float*)d_in[3];
    const float* IUw     = (const float*)d_in[4];
    const float* KUw     = (const float*)d_in[5];
    const float* lmbda   = (const float*)d_in[6];
    const float* conf    = (const float*)d_in[7];
    const float* known   = (const float*)d_in[8];
    const float* kToU    = (const float*)d_in[9];
    const int*   wr      = (const int*)d_in[10];
    const int*   wc      = (const int*)d_in[11];
    const float* wd      = (const float*)d_in[12];
    const int*   locInd  = (const int*)d_in[13];
    const float* locFl   = (const float*)d_in[14];
    const int*   iuInd   = (const int*)d_in[15];
    const float* iuFl    = (const float*)d_in[16];
    const int*   iuNb    = (const int*)d_in[17];

    int N    = in_sizes[2];
    int NNZ  = in_sizes[10];
    int MLOC = in_sizes[13];
    int MIU  = in_sizes[15];

    float* A = (float*)d_out;
    float* b = A + (size_t)N * N;
    long total = (long)out_size;

    const int T = 256;
    int half     = (NNZ + 1) / 2;
    int nbCM     = (half + T - 1) / T;
    int cmStride = nbCM * T;
    int nbLoc    = (MLOC * 9 + T - 1) / T;
    int nbIu     = (MIU * 5 + T - 1) / T;
    k1_bin<<<nbCM + nbLoc + nbIu, T>>>(wr, wc, wd, CMw, NNZ, cmStride,
                                       locInd, locFl, LOCw, MLOC, width,
                                       iuInd, iuFl, iuNb, IUw, MIU,
                                       nbCM, nbLoc);

    k2_rows<<<N, 128>>>(A, b, N, KUw, conf, lmbda, known, kToU);

    k3_reset<<<(N + 255) / 256, 256>>>(A, N, total);
}

// round 10
// speedup vs baseline: 1.4966x; 1.0734x over previous
#include <cuda_runtime.h>

#define CAPR 64
#define CAPC 64
#define CAPE 320
#define MAXN 4096
#define PAD  32      // one counter per 128B L2 line

// -------- static scratch (no allocations allowed) --------
// Zero-initialized at module load; counters reset in k2/k3 so every call
// (including graph replays) observes zeroed state.
// All hot counters are padded to one per 128-byte line to avoid LTS
// line-level serialization under heavy atomic traffic.
__device__ int   g_cnt_row[MAXN * PAD];    // CM CSR bucket counts
__device__ int2  g_rbuf[MAXN * CAPR];      // (col, bits(-v))
__device__ int   g_cnt_col[MAXN * PAD];    // CM contributor counts
__device__ int2  g_cbuf[MAXN * CAPC];      // (src row k, bits(-v))
__device__ int   g_cnt_ext[MAXN * PAD];    // LOC/IU off-diag items per row
__device__ int2  g_ebuf[MAXN * CAPE];      // (col, bits(val))
__device__ float g_rowsum[MAXN * PAD];     // S_k of CM row k
__device__ float g_diag[MAXN * PAD];       // LOC/IU diagonal accumulation

// ============ K1: bin everything ============================================
__global__ void k1_bin(const int* __restrict__ row,
                       const int* __restrict__ col,
                       const float* __restrict__ data,
                       const float* __restrict__ cmw, int nnz,
                       const int* __restrict__ locInd,
                       const float* __restrict__ locFl,
                       const float* __restrict__ locw,
                       int mloc, const int* __restrict__ widthp,
                       const int* __restrict__ iuInd,
                       const float* __restrict__ iuFl,
                       const int* __restrict__ iuNb,
                       const float* __restrict__ iuw,
                       int miu, int nbCM, int nbLoc) {
    int b = blockIdx.x;
    if (b < nbCM) {
        int t = b * blockDim.x + threadIdx.x;
        if (t >= nnz) return;
        int r = row[t];
        int c = col[t];
        float v = data[t] * cmw[r];
        int s = atomicAdd(&g_cnt_row[r * PAD], 1);
        if (s < CAPR) g_rbuf[r * CAPR + s] = make_int2(c, __float_as_int(-v));
        int s2 = atomicAdd(&g_cnt_col[c * PAD], 1);
        if (s2 < CAPC) g_cbuf[c * CAPC + s2] = make_int2(r, __float_as_int(-v));
        atomicAdd(&g_rowsum[r * PAD], v);       // no-return RED
        return;
    }
    b -= nbCM;
    if (b < nbLoc) {
        int t = b * blockDim.x + threadIdx.x;
        if (t >= mloc * 9) return;
        int mi = t / 9, j = t - mi * 9;
        int W = widthp[0];
        int ind = locInd[mi];
        float h = 0.5f * locFl[(size_t)j * 9 * mloc + mi] * locw[ind];
        int r = ind - 1 - W;
        int c = ind + (j / 3 - 1) + (j % 3 - 1) * W;
        int s = atomicAdd(&g_cnt_ext[r * PAD], 1);
        if (s < CAPE) g_ebuf[r * CAPE + s] = make_int2(c, __float_as_int(-h));
        int s2 = atomicAdd(&g_cnt_ext[c * PAD], 1);
        if (s2 < CAPE) g_ebuf[c * CAPE + s2] = make_int2(r, __float_as_int(-h));
        atomicAdd(&g_diag[r * PAD], h);         // no-return REDs
        atomicAdd(&g_diag[c * PAD], h);
        return;
    }
    b -= nbLoc;
    {
        int t = b * blockDim.x + threadIdx.x;
        if (t >= miu * 5) return;
        int mi = t / 5, j = t - mi * 5;
        int r = iuInd[mi];
        float h = 0.5f * iuFl[mi * 5 + j] * iuw[r];
        int c = iuNb[mi * 5 + j];
        int s = atomicAdd(&g_cnt_ext[r * PAD], 1);
        if (s < CAPE) g_ebuf[r * CAPE + s] = make_int2(c, __float_as_int(-h));
        int s2 = atomicAdd(&g_cnt_ext[c * PAD], 1);
        if (s2 < CAPE) g_ebuf[c * CAPE + s2] = make_int2(r, __float_as_int(-h));
        atomicAdd(&g_diag[r * PAD], h);
        atomicAdd(&g_diag[c * PAD], h);
    }
}

// ============ K2: one 128-thread block builds one complete row of A =========
// Plain (write-back) stores: A fits in L2 (67MB < 126MB), so dirty lines can
// stay cached at kernel end instead of being forced to DRAM inside the kernel.
__global__ void __launch_bounds__(128) k2_rows(
        float* __restrict__ A, float* __restrict__ bvec, int n,
        const float* __restrict__ ku, const float* __restrict__ conf,
        const float* __restrict__ lmb, const float* __restrict__ known,
        const float* __restrict__ kToU) {
    __shared__ float rowbuf[MAXN];
    __shared__ int   skk[CAPC];
    __shared__ float scf[CAPC];

    int a = blockIdx.x;
    int tid = threadIdx.x;
    int warp = tid >> 5, lane = tid & 31;

    int cc = g_cnt_col[a * PAD]; if (cc > CAPC) cc = CAPC;
    int ce = g_cnt_ext[a * PAD]; if (ce > CAPE) ce = CAPE;

    float4* rb4 = (float4*)rowbuf;
    float4 z = make_float4(0.f, 0.f, 0.f, 0.f);
    int n4 = n >> 2;
    #pragma unroll 4
    for (int i = tid; i < n4; i += 128) rb4[i] = z;

    if (tid < cc) {
        int2 e = g_cbuf[a * CAPC + tid];
        skk[tid] = e.x;
        scf[tid] = __int_as_float(e.y);
    }
    __syncthreads();

    // CM contributors: A[a,:] += coef_k * Lcm[k,:] (it == cc is the virtual
    // diagonal contributor of source row a, coefficient S_a).
    for (int it = warp; it <= cc; it += 4) {
        bool virt = (it == cc);
        int k      = virt ? a : skk[it];
        float Sk   = g_rowsum[k * PAD];
        float coef = virt ? Sk : scf[it];
        int ck = g_cnt_row[k * PAD]; if (ck > CAPR) ck = CAPR;
        if (lane < ck) {
            int2 e = g_rbuf[k * CAPR + lane];
            atomicAdd(&rowbuf[e.x], coef * __int_as_float(e.y));
        }
        if (lane + 32 < ck) {
            int2 e = g_rbuf[k * CAPR + lane + 32];
            atomicAdd(&rowbuf[e.x], coef * __int_as_float(e.y));
        }
        if (lane == 0) atomicAdd(&rowbuf[k], coef * Sk);
    }

    // LOC/IU off-diagonal items
    for (int i = tid; i < ce; i += 128) {
        int2 e = g_ebuf[a * CAPE + i];
        atomicAdd(&rowbuf[e.x], __int_as_float(e.y));
    }

    // diagonal (LOC/IU accumulated + regularization) + b; reset row-private state
    if (tid == 0) {
        float d = ku[a] * conf[a] + lmb[0] * known[a];
        atomicAdd(&rowbuf[a], d + g_diag[a * PAD]);
        bvec[a] = d * kToU[a];
        g_diag[a * PAD]    = 0.f;
        g_cnt_col[a * PAD] = 0;
        g_cnt_ext[a * PAD] = 0;
    }
    __syncthreads();

    float4* dst = (float4*)(A + (size_t)a * n);
    #pragma unroll 4
    for (int i = tid; i < n4; i += 128) dst[i] = rb4[i];
}

// ============ K3: reset cross-block-read scratch + tail-poison cleanup ======
__global__ void k3_reset(float* __restrict__ out, int n, long total) {
    int i = blockIdx.x * blockDim.x + threadIdx.x;
    if (i < n) { g_cnt_row[i * PAD] = 0; g_rowsum[i * PAD] = 0.f; }
    long base = (long)n * n + n;
    long extra = total - base;
    if (extra > 0) {
        long p = (long)blockIdx.x * blockDim.x + threadIdx.x;
        if (p < extra) out[base + p] = 0.f;
    }
}

extern "C" void kernel_launch(void* const* d_in, const int* in_sizes, int n_in,
                              void* d_out, int out_size) {
    // 0 height, 1 width, 2 CM_weights, 3 LOC_weights, 4 IU_weights,
    // 5 KU_weights, 6 lmbda, 7 kToUconf, 8 known, 9 kToU,
    // 10 Wcm_row, 11 Wcm_col, 12 Wcm_data, 13 LOC_inInd, 14 LOC_flows,
    // 15 IU_inInd, 16 IU_flows, 17 IU_neighInd
    const int*   width   = (const int*)d_in[1];
    const float* CMw     = (const float*)d_in[2];
    const float* LOCw    = (const float*)d_in[3];
    const float* IUw     = (const float*)d_in[4];
    const float* KUw     = (const float*)d_in[5];
    const float* lmbda   = (const float*)d_in[6];
    const float* conf    = (const float*)d_in[7];
    const float* known   = (const float*)d_in[8];
    const float* kToU    = (const float*)d_in[9];
    const int*   wr      = (const int*)d_in[10];
    const int*   wc      = (const int*)d_in[11];
    const float* wd      = (const float*)d_in[12];
    const int*   locInd  = (const int*)d_in[13];
    const float* locFl   = (const float*)d_in[14];
    const int*   iuInd   = (const int*)d_in[15];
    const float* iuFl    = (const float*)d_in[16];
    const int*   iuNb    = (const int*)d_in[17];

    int N    = in_sizes[2];
    int NNZ  = in_sizes[10];
    int MLOC = in_sizes[13];
    int MIU  = in_sizes[15];

    float* A = (float*)d_out;
    float* b = A + (size_t)N * N;
    long total = (long)out_size;

    const int T = 256;
    int nbCM  = (NNZ + T - 1) / T;
    int nbLoc = (MLOC * 9 + T - 1) / T;
    int nbIu  = (MIU * 5 + T - 1) / T;
    k1_bin<<<nbCM + nbLoc + nbIu, T>>>(wr, wc, wd, CMw, NNZ,
                                       locInd, locFl, LOCw, MLOC, width,
                                       iuInd, iuFl, iuNb, IUw, MIU,
                                       nbCM, nbLoc);

    k2_rows<<<N, 128>>>(A, b, N, KUw, conf, lmbda, known, kToU);

    k3_reset<<<(N + 255) / 256, 256>>>(A, N, total);
}